// round 10
// baseline (speedup 1.0000x reference)
#include <cuda_runtime.h>
#include <stdint.h>

#define NPTS 8192
#define MAXE (64 * NPTS)
#define WPR  (NPTS / 32)     // 256 mask words per row
#define EMIT_BLOCKS 1024     // 8 warps/block * 1024 = 8192 row-warps
#define FILL_BLOCKS 512      // 512*256 threads*4 elems = 524288 = MAXE

// Static scratch (no allocations allowed)
__device__ float4 g_pos4[NPTS];
__device__ __align__(16) unsigned g_mask[NPTS * WPR];   // 8 MB bitmask
__device__ int g_cnt[NPTS];
__device__ int g_off[NPTS + 1];

// ---------------------------------------------------------------------------
// Pass A: pack (x, y, z, sq) — full fp32.
// sq replicates jnp.sum(pos*pos,-1): ((x^2 + y^2) + z^2), separate rn ops.
// ---------------------------------------------------------------------------
__global__ void pack_kernel(const float* __restrict__ pos) {
    int i = blockIdx.x * blockDim.x + threadIdx.x;
    if (i < NPTS) {
        float x = pos[3 * i + 0];
        float y = pos[3 * i + 1];
        float z = pos[3 * i + 2];
        float sq = __fadd_rn(__fadd_rn(__fmul_rn(x, x), __fmul_rn(y, y)),
                             __fmul_rn(z, z));
        g_pos4[i] = make_float4(x, y, z, sq);
    }
}

// ---------------------------------------------------------------------------
// Pass B: mask + count, 4 rows per warp (amortize the pos4 load 4x).
// Bit-exact model (validated R5):
//   dot = fma(z,z', fma(y,y', rn(x*x'))); s = rn(sq_i+sq_j);
//   d2 = fma(-2, dot, s);  edge <=> d2 < pred(25) = 0x41C7FFFF (&& j != i).
// Diagonal: d2(i,i) ~ +-0.008 < T always -> bit always set; cleared after the
// loop (all 4 rows' diag bits are in word i0>>5 since i0 % 4 == 0).
// ---------------------------------------------------------------------------
__global__ void mask_kernel() {
    int gw   = (blockIdx.x * blockDim.x + threadIdx.x) >> 5;  // 0..2047
    int lane = threadIdx.x & 31;
    int i0 = gw * 4;
    const float4 p0 = g_pos4[i0 + 0];
    const float4 p1 = g_pos4[i0 + 1];
    const float4 p2 = g_pos4[i0 + 2];
    const float4 p3 = g_pos4[i0 + 3];
    const float T = __uint_as_float(0x41C7FFFFu);  // pred(25.0f)

    int c0 = 0, c1 = 0, c2 = 0, c3 = 0;
    unsigned* mrow = g_mask + (size_t)i0 * WPR;
#pragma unroll 4
    for (int c = 0; c < WPR; ++c) {
        float4 pj = g_pos4[c * 32 + lane];

        float d0 = __fmaf_rn(-2.0f,
                     __fmaf_rn(p0.z, pj.z, __fmaf_rn(p0.y, pj.y, __fmul_rn(p0.x, pj.x))),
                     __fadd_rn(p0.w, pj.w));
        float d1 = __fmaf_rn(-2.0f,
                     __fmaf_rn(p1.z, pj.z, __fmaf_rn(p1.y, pj.y, __fmul_rn(p1.x, pj.x))),
                     __fadd_rn(p1.w, pj.w));
        float d2 = __fmaf_rn(-2.0f,
                     __fmaf_rn(p2.z, pj.z, __fmaf_rn(p2.y, pj.y, __fmul_rn(p2.x, pj.x))),
                     __fadd_rn(p2.w, pj.w));
        float d3 = __fmaf_rn(-2.0f,
                     __fmaf_rn(p3.z, pj.z, __fmaf_rn(p3.y, pj.y, __fmul_rn(p3.x, pj.x))),
                     __fadd_rn(p3.w, pj.w));

        unsigned b0 = __ballot_sync(0xffffffffu, d0 < T);
        unsigned b1 = __ballot_sync(0xffffffffu, d1 < T);
        unsigned b2 = __ballot_sync(0xffffffffu, d2 < T);
        unsigned b3 = __ballot_sync(0xffffffffu, d3 < T);

        if (lane == 0) mrow[0 * WPR + c] = b0;
        if (lane == 1) mrow[1 * WPR + c] = b1;
        if (lane == 2) mrow[2 * WPR + c] = b2;
        if (lane == 3) mrow[3 * WPR + c] = b3;

        c0 += __popc(b0); c1 += __popc(b1);
        c2 += __popc(b2); c3 += __popc(b3);
    }

    // Clear the (always-set) diagonal bits and fix counts.
    int cd = i0 >> 5;
    if (lane < 4) {
        size_t idx = (size_t)lane * WPR + cd;
        unsigned w = mrow[idx];
        mrow[idx] = w & ~(1u << ((i0 + lane) & 31));
    }
    if (lane == 0) {
        g_cnt[i0 + 0] = c0 - 1;
        g_cnt[i0 + 1] = c1 - 1;
        g_cnt[i0 + 2] = c2 - 1;
        g_cnt[i0 + 3] = c3 - 1;
    }
}

// ---------------------------------------------------------------------------
// Pass C: exclusive scan of 8192 row counts, single block of 1024 threads.
// ---------------------------------------------------------------------------
__global__ void scan_kernel() {
    __shared__ int warp_sums[32];
    int tid  = threadIdx.x;          // 1024 threads
    int lane = tid & 31;
    int wid  = tid >> 5;

    int base = tid * 8;
    int v[8];
    int s = 0;
#pragma unroll
    for (int k = 0; k < 8; ++k) { v[k] = g_cnt[base + k]; s += v[k]; }

    int x = s;
#pragma unroll
    for (int d = 1; d < 32; d <<= 1) {
        int y = __shfl_up_sync(0xffffffffu, x, d);
        if (lane >= d) x += y;
    }
    if (lane == 31) warp_sums[wid] = x;
    __syncthreads();
    if (wid == 0) {
        int w = warp_sums[lane];
        int xx = w;
#pragma unroll
        for (int d = 1; d < 32; d <<= 1) {
            int y = __shfl_up_sync(0xffffffffu, xx, d);
            if (lane >= d) xx += y;
        }
        warp_sums[lane] = xx;
    }
    __syncthreads();

    int warp_excl = (wid == 0) ? 0 : warp_sums[wid - 1];
    int run = warp_excl + (x - s);   // exclusive prefix for this thread
#pragma unroll
    for (int k = 0; k < 8; ++k) { g_off[base + k] = run; run += v[k]; }
    if (tid == 1023) g_off[NPTS] = run;
}

// ---------------------------------------------------------------------------
// Pass D: emit (blocks < EMIT_BLOCKS) + tail fill (blocks >= EMIT_BLOCKS).
// Emit: one warp per row; lane L owns mask words [8L, 8L+8) i.e. cols
// [256L, 256L+256) -> row-major order preserved. Output is float32.
// Fill: float4 stores of -1.0f beyond total edge count (both planes).
// ---------------------------------------------------------------------------
__global__ void emit_fill_kernel(float* __restrict__ out) {
    if (blockIdx.x >= EMIT_BLOCKS) {
        int b  = blockIdx.x - EMIT_BLOCKS;
        int e0 = (b * 256 + threadIdx.x) * 4;
        int total = g_off[NPTS];
        if (e0 + 4 > total) {
            if (e0 >= total) {
                float4 v = make_float4(-1.0f, -1.0f, -1.0f, -1.0f);
                *(float4*)(out + e0)        = v;
                *(float4*)(out + MAXE + e0) = v;
            } else {
#pragma unroll
                for (int k = 0; k < 4; ++k) {
                    if (e0 + k >= total) {
                        out[e0 + k]        = -1.0f;
                        out[MAXE + e0 + k] = -1.0f;
                    }
                }
            }
        }
        return;
    }

    int gwarp = (blockIdx.x * blockDim.x + threadIdx.x) >> 5;
    int lane  = threadIdx.x & 31;
    const int i = gwarp;

    const uint4* mrow = (const uint4*)(g_mask + (size_t)i * WPR);
    uint4 a = mrow[lane * 2 + 0];
    uint4 b = mrow[lane * 2 + 1];
    unsigned w[8] = {a.x, a.y, a.z, a.w, b.x, b.y, b.z, b.w};

    int pc = 0;
#pragma unroll
    for (int k = 0; k < 8; ++k) pc += __popc(w[k]);

    int x = pc;
#pragma unroll
    for (int d = 1; d < 32; d <<= 1) {
        int y = __shfl_up_sync(0xffffffffu, x, d);
        if (lane >= d) x += y;
    }
    int off = g_off[i] + (x - pc);

    float fi = (float)i;
    int colbase = lane * 256;
#pragma unroll
    for (int k = 0; k < 8; ++k) {
        unsigned ww = w[k];
        int cb = colbase + k * 32;
        while (ww) {
            int bit = __ffs(ww) - 1;
            out[off]        = fi;                  // rows plane
            out[MAXE + off] = (float)(cb + bit);   // cols plane
            ++off;
            ww &= ww - 1;
        }
    }
}

extern "C" void kernel_launch(void* const* d_in, const int* in_sizes, int n_in,
                              void* d_out, int out_size) {
    const float* pos = (const float*)d_in[0];
    float* out = (float*)d_out;

    pack_kernel<<<(NPTS + 255) / 256, 256>>>(pos);
    mask_kernel<<<256, 256>>>();               // 2048 warps, 4 rows each
    scan_kernel<<<1, 1024>>>();
    emit_fill_kernel<<<EMIT_BLOCKS + FILL_BLOCKS, 256>>>(out);
}

// round 12
// speedup vs baseline: 1.4375x; 1.4375x over previous
#include <cuda_runtime.h>
#include <stdint.h>

#define NPTS 8192
#define MAXE (64 * NPTS)
#define WPR  (NPTS / 32)     // 256 mask words per row
#define QSPLIT 4
#define CPQ  (WPR / QSPLIT)  // 64 mask words per warp (column quarter)
#define EMIT_BLOCKS 1024     // 8 warps/block * 1024 = 8192 row-warps
#define FILL_BLOCKS 512      // 512*256 threads*4 elems = 524288 = MAXE

// Static scratch (no allocations allowed)
__device__ float4 g_pos4[NPTS];
__device__ __align__(16) unsigned g_mask[NPTS * WPR];   // 8 MB bitmask
__device__ __align__(16) int g_cnt4[NPTS * QSPLIT];     // partial counts [row][q]
__device__ int g_off[NPTS + 1];

// ---------------------------------------------------------------------------
// Pass A: pack (x, y, z, sq) — full fp32.
// sq replicates jnp.sum(pos*pos,-1): ((x^2 + y^2) + z^2), separate rn ops.
// ---------------------------------------------------------------------------
__global__ void pack_kernel(const float* __restrict__ pos) {
    int i = blockIdx.x * blockDim.x + threadIdx.x;
    if (i < NPTS) {
        float x = pos[3 * i + 0];
        float y = pos[3 * i + 1];
        float z = pos[3 * i + 2];
        float sq = __fadd_rn(__fadd_rn(__fmul_rn(x, x), __fmul_rn(y, y)),
                             __fmul_rn(z, z));
        g_pos4[i] = make_float4(x, y, z, sq);
    }
}

// ---------------------------------------------------------------------------
// Pass B: mask + count. 2D tiling: each warp = 4-row block x 1 column quarter
// (64 words). 8192 warps total -> R5-level occupancy (latency hidden) with
// R10-level L1 reuse (4 rows per pj load).
// Bit-exact model (validated R5):
//   dot = fma(z,z', fma(y,y', rn(x*x'))); s = rn(sq_i+sq_j);
//   d2 = fma(-2, dot, s);  edge <=> d2 < pred(25) = 0x41C7FFFF (&& j != i).
// Diagonal bit (always set since d2(i,i) ~ +-0.008 < T): cleared by the warp
// whose quarter owns word i0>>5; its partial counts are decremented.
// ---------------------------------------------------------------------------
__global__ void mask_kernel() {
    int gw   = (blockIdx.x * blockDim.x + threadIdx.x) >> 5;  // 0..8191
    int lane = threadIdx.x & 31;
    int rb = gw >> 2;          // row block 0..2047
    int q  = gw & 3;           // column quarter 0..3
    int i0 = rb * 4;
    const float4 p0 = g_pos4[i0 + 0];
    const float4 p1 = g_pos4[i0 + 1];
    const float4 p2 = g_pos4[i0 + 2];
    const float4 p3 = g_pos4[i0 + 3];
    const float T = __uint_as_float(0x41C7FFFFu);  // pred(25.0f)

    int c0 = 0, c1 = 0, c2 = 0, c3 = 0;
    unsigned* mrow = g_mask + (size_t)i0 * WPR;
    const int cbeg = q * CPQ;
#pragma unroll 4
    for (int cc = 0; cc < CPQ; ++cc) {
        int c = cbeg + cc;
        float4 pj = g_pos4[c * 32 + lane];

        float d0 = __fmaf_rn(-2.0f,
                     __fmaf_rn(p0.z, pj.z, __fmaf_rn(p0.y, pj.y, __fmul_rn(p0.x, pj.x))),
                     __fadd_rn(p0.w, pj.w));
        float d1 = __fmaf_rn(-2.0f,
                     __fmaf_rn(p1.z, pj.z, __fmaf_rn(p1.y, pj.y, __fmul_rn(p1.x, pj.x))),
                     __fadd_rn(p1.w, pj.w));
        float d2 = __fmaf_rn(-2.0f,
                     __fmaf_rn(p2.z, pj.z, __fmaf_rn(p2.y, pj.y, __fmul_rn(p2.x, pj.x))),
                     __fadd_rn(p2.w, pj.w));
        float d3 = __fmaf_rn(-2.0f,
                     __fmaf_rn(p3.z, pj.z, __fmaf_rn(p3.y, pj.y, __fmul_rn(p3.x, pj.x))),
                     __fadd_rn(p3.w, pj.w));

        unsigned b0 = __ballot_sync(0xffffffffu, d0 < T);
        unsigned b1 = __ballot_sync(0xffffffffu, d1 < T);
        unsigned b2 = __ballot_sync(0xffffffffu, d2 < T);
        unsigned b3 = __ballot_sync(0xffffffffu, d3 < T);

        if (lane == 0) mrow[0 * WPR + c] = b0;
        if (lane == 1) mrow[1 * WPR + c] = b1;
        if (lane == 2) mrow[2 * WPR + c] = b2;
        if (lane == 3) mrow[3 * WPR + c] = b3;

        c0 += __popc(b0); c1 += __popc(b1);
        c2 += __popc(b2); c3 += __popc(b3);
    }

    // Diagonal: word index cd = i0>>5 holds all 4 rows' diag bits
    // (i0 % 32 <= 28). Only the owning quarter clears + decrements.
    int cd = i0 >> 5;
    int own = (cd >= cbeg && cd < cbeg + CPQ) ? 1 : 0;
    if (own && lane < 4) {
        size_t idx = (size_t)lane * WPR + cd;
        unsigned w = mrow[idx];
        mrow[idx] = w & ~(1u << ((i0 + lane) & 31));
    }
    if (lane == 0) {
        g_cnt4[(i0 + 0) * QSPLIT + q] = c0 - own;
        g_cnt4[(i0 + 1) * QSPLIT + q] = c1 - own;
        g_cnt4[(i0 + 2) * QSPLIT + q] = c2 - own;
        g_cnt4[(i0 + 3) * QSPLIT + q] = c3 - own;
    }
}

// ---------------------------------------------------------------------------
// Pass C: exclusive scan of 8192 row counts (each = sum of 4 partials),
// single block of 1024 threads.
// ---------------------------------------------------------------------------
__global__ void scan_kernel() {
    __shared__ int warp_sums[32];
    int tid  = threadIdx.x;          // 1024 threads
    int lane = tid & 31;
    int wid  = tid >> 5;

    int base = tid * 8;
    int v[8];
    int s = 0;
#pragma unroll
    for (int k = 0; k < 8; ++k) {
        int4 p = ((const int4*)g_cnt4)[base + k];
        v[k] = p.x + p.y + p.z + p.w;
        s += v[k];
    }

    int x = s;
#pragma unroll
    for (int d = 1; d < 32; d <<= 1) {
        int y = __shfl_up_sync(0xffffffffu, x, d);
        if (lane >= d) x += y;
    }
    if (lane == 31) warp_sums[wid] = x;
    __syncthreads();
    if (wid == 0) {
        int w = warp_sums[lane];
        int xx = w;
#pragma unroll
        for (int d = 1; d < 32; d <<= 1) {
            int y = __shfl_up_sync(0xffffffffu, xx, d);
            if (lane >= d) xx += y;
        }
        warp_sums[lane] = xx;
    }
    __syncthreads();

    int warp_excl = (wid == 0) ? 0 : warp_sums[wid - 1];
    int run = warp_excl + (x - s);   // exclusive prefix for this thread
#pragma unroll
    for (int k = 0; k < 8; ++k) { g_off[base + k] = run; run += v[k]; }
    if (tid == 1023) g_off[NPTS] = run;
}

// ---------------------------------------------------------------------------
// Pass D: emit (blocks < EMIT_BLOCKS) + tail fill (blocks >= EMIT_BLOCKS).
// Emit: one warp per row; lane L owns mask words [8L, 8L+8) i.e. cols
// [256L, 256L+256) -> row-major order preserved. Output is float32.
// Fill: float4 stores of -1.0f beyond total edge count (both planes).
// ---------------------------------------------------------------------------
__global__ void emit_fill_kernel(float* __restrict__ out) {
    if (blockIdx.x >= EMIT_BLOCKS) {
        int b  = blockIdx.x - EMIT_BLOCKS;
        int e0 = (b * 256 + threadIdx.x) * 4;
        int total = g_off[NPTS];
        if (e0 + 4 > total) {
            if (e0 >= total) {
                float4 v = make_float4(-1.0f, -1.0f, -1.0f, -1.0f);
                *(float4*)(out + e0)        = v;
                *(float4*)(out + MAXE + e0) = v;
            } else {
#pragma unroll
                for (int k = 0; k < 4; ++k) {
                    if (e0 + k >= total) {
                        out[e0 + k]        = -1.0f;
                        out[MAXE + e0 + k] = -1.0f;
                    }
                }
            }
        }
        return;
    }

    int gwarp = (blockIdx.x * blockDim.x + threadIdx.x) >> 5;
    int lane  = threadIdx.x & 31;
    const int i = gwarp;

    const uint4* mrow = (const uint4*)(g_mask + (size_t)i * WPR);
    uint4 a = mrow[lane * 2 + 0];
    uint4 b = mrow[lane * 2 + 1];
    unsigned w[8] = {a.x, a.y, a.z, a.w, b.x, b.y, b.z, b.w};

    int pc = 0;
#pragma unroll
    for (int k = 0; k < 8; ++k) pc += __popc(w[k]);

    int x = pc;
#pragma unroll
    for (int d = 1; d < 32; d <<= 1) {
        int y = __shfl_up_sync(0xffffffffu, x, d);
        if (lane >= d) x += y;
    }
    int off = g_off[i] + (x - pc);

    float fi = (float)i;
    int colbase = lane * 256;
#pragma unroll
    for (int k = 0; k < 8; ++k) {
        unsigned ww = w[k];
        int cb = colbase + k * 32;
        while (ww) {
            int bit = __ffs(ww) - 1;
            out[off]        = fi;                  // rows plane
            out[MAXE + off] = (float)(cb + bit);   // cols plane
            ++off;
            ww &= ww - 1;
        }
    }
}

extern "C" void kernel_launch(void* const* d_in, const int* in_sizes, int n_in,
                              void* d_out, int out_size) {
    const float* pos = (const float*)d_in[0];
    float* out = (float*)d_out;

    pack_kernel<<<(NPTS + 255) / 256, 256>>>(pos);
    mask_kernel<<<1024, 256>>>();              // 8192 warps: 4 rows x 1/4 cols
    scan_kernel<<<1, 1024>>>();
    emit_fill_kernel<<<EMIT_BLOCKS + FILL_BLOCKS, 256>>>(out);
}

// round 17
// speedup vs baseline: 4.0496x; 2.8171x over previous
#include <cuda_runtime.h>
#include <stdint.h>

#define NPTS 8192
#define MAXE (64 * NPTS)
#define WPR  (NPTS / 32)     // 256 mask words per row
#define GRID 9
#define NCELLS (GRID * GRID * GRID)   // 729
#define CINV (float(GRID) / 50.0f)    // cells of 5.556 > 5.001 safety radius
#define EMIT_BLOCKS 1024     // 8 warps/block * 1024 = 8192 row-warps
#define FILL_BLOCKS 512      // 512*256 threads*4 elems = 524288 = MAXE

// Static scratch (no allocations allowed)
__device__ float4 g_pos4[NPTS];
__device__ __align__(16) unsigned g_mask[NPTS * WPR];   // 8 MB bitmask
__device__ int g_cnt[NPTS];
__device__ int g_off[NPTS + 1];
__device__ int g_cellcnt[NCELLS];
__device__ int g_cellstart[NCELLS + 1];
__device__ int g_cellfill[NCELLS];
__device__ int g_cid[NPTS];
__device__ float4 g_spos4[NPTS];   // cell-sorted positions
__device__ int    g_sidx[NPTS];    // cell-sorted original indices

// ---------------------------------------------------------------------------
// Pass 0: zero the cell counters (statics persist across graph replays).
// ---------------------------------------------------------------------------
__global__ void zero_kernel() {
    int t = threadIdx.x;
    if (t < NCELLS) g_cellcnt[t] = 0;
}

// ---------------------------------------------------------------------------
// Pass A: pack (x, y, z, sq) + cell id + cell histogram.
// sq replicates jnp.sum(pos*pos,-1): ((x^2+y^2)+z^2), separate rn ops.
// ---------------------------------------------------------------------------
__global__ void pack_kernel(const float* __restrict__ pos) {
    int i = blockIdx.x * blockDim.x + threadIdx.x;
    if (i < NPTS) {
        float x = pos[3 * i + 0];
        float y = pos[3 * i + 1];
        float z = pos[3 * i + 2];
        float sq = __fadd_rn(__fadd_rn(__fmul_rn(x, x), __fmul_rn(y, y)),
                             __fmul_rn(z, z));
        g_pos4[i] = make_float4(x, y, z, sq);
        int cx = (int)(x * CINV), cy = (int)(y * CINV), cz = (int)(z * CINV);
        int cid = (cz * GRID + cy) * GRID + cx;
        g_cid[i] = cid;
        atomicAdd(&g_cellcnt[cid], 1);
    }
}

// ---------------------------------------------------------------------------
// Pass B: exclusive scan of 729 cell counts (1 block, 1024 threads).
// Writes g_cellstart[0..729] and g_cellfill (scatter cursors).
// ---------------------------------------------------------------------------
__global__ void cell_scan_kernel() {
    __shared__ int ws[32];
    int t = threadIdx.x, lane = t & 31, wid = t >> 5;
    int v = (t < NCELLS) ? g_cellcnt[t] : 0;
    int x = v;
#pragma unroll
    for (int d = 1; d < 32; d <<= 1) {
        int y = __shfl_up_sync(0xffffffffu, x, d);
        if (lane >= d) x += y;
    }
    if (lane == 31) ws[wid] = x;
    __syncthreads();
    if (wid == 0) {
        int w = ws[lane], xx = w;
#pragma unroll
        for (int d = 1; d < 32; d <<= 1) {
            int y = __shfl_up_sync(0xffffffffu, xx, d);
            if (lane >= d) xx += y;
        }
        ws[lane] = xx;
    }
    __syncthreads();
    int excl = ((wid == 0) ? 0 : ws[wid - 1]) + (x - v);
    if (t <= NCELLS) g_cellstart[t] = excl;
    if (t < NCELLS)  g_cellfill[t] = excl;
}

// ---------------------------------------------------------------------------
// Pass C: scatter points into cell-sorted order (order in cell irrelevant —
// hits become BITS, which restore (row,col) order exactly).
// ---------------------------------------------------------------------------
__global__ void scatter_kernel() {
    int i = blockIdx.x * blockDim.x + threadIdx.x;
    if (i < NPTS) {
        int dst = atomicAdd(&g_cellfill[g_cid[i]], 1);
        g_spos4[dst] = g_pos4[i];
        g_sidx[dst] = i;
    }
}

// ---------------------------------------------------------------------------
// Pass D: mask via cell list. One warp per row. The 27 neighbor cells form 9
// contiguous x-runs of the sorted array (~25 pts each). Bit-exact decision
// (validated R5): d2 = fma(-2, fma(z,z',fma(y,y',rn(x*x'))), rn(sq_i+sq_j));
// edge <=> d2 < pred(25) = 0x41C7FFFF && j != i.
// Coverage: accepted pairs have true dist < 5.001 < cell edge 5.556.
// ---------------------------------------------------------------------------
__global__ void mask_cell_kernel() {
    __shared__ __align__(16) unsigned smask[8][WPR];   // 8 KB
    int wid  = threadIdx.x >> 5;
    int lane = threadIdx.x & 31;
    int i = blockIdx.x * 8 + wid;
    unsigned* m = smask[wid];
#pragma unroll
    for (int k = 0; k < 8; ++k) m[k * 32 + lane] = 0;
    __syncwarp();

    const float4 pi = g_pos4[i];
    const float T = __uint_as_float(0x41C7FFFFu);  // pred(25.0f)
    int cx = (int)(pi.x * CINV), cy = (int)(pi.y * CINV), cz = (int)(pi.z * CINV);
    int x0 = cx > 0 ? cx - 1 : 0;
    int x1 = cx < GRID - 1 ? cx + 1 : GRID - 1;

    int cnt = 0;
    for (int dz = -1; dz <= 1; ++dz) {
        int cz2 = cz + dz;
        if ((unsigned)cz2 >= GRID) continue;
        for (int dy = -1; dy <= 1; ++dy) {
            int cy2 = cy + dy;
            if ((unsigned)cy2 >= GRID) continue;
            int base = (cz2 * GRID + cy2) * GRID;
            int s = g_cellstart[base + x0];
            int e = g_cellstart[base + x1 + 1];
            for (int k0 = s; k0 < e; k0 += 32) {
                int k = k0 + lane;
                bool hit = false;
                int j = 0;
                if (k < e) {
                    float4 pj = g_spos4[k];
                    j = g_sidx[k];
                    float d2 = __fmaf_rn(-2.0f,
                                 __fmaf_rn(pi.z, pj.z,
                                 __fmaf_rn(pi.y, pj.y, __fmul_rn(pi.x, pj.x))),
                                 __fadd_rn(pi.w, pj.w));
                    hit = (d2 < T) && (j != i);
                }
                if (hit) atomicOr(&m[j >> 5], 1u << (j & 31));
                cnt += __popc(__ballot_sync(0xffffffffu, hit));
            }
        }
    }
    __syncwarp();

    // Stream the row mask to global (lane L owns words [8L, 8L+8)).
    uint4* grow = (uint4*)(g_mask + (size_t)i * WPR);
    const uint4* srow = (const uint4*)m;
#pragma unroll
    for (int k = 0; k < 2; ++k) grow[lane * 2 + k] = srow[lane * 2 + k];
    if (lane == 0) g_cnt[i] = cnt;
}

// ---------------------------------------------------------------------------
// Pass E: exclusive scan of 8192 row counts, single block of 1024 threads.
// ---------------------------------------------------------------------------
__global__ void scan_kernel() {
    __shared__ int warp_sums[32];
    int tid  = threadIdx.x;          // 1024 threads
    int lane = tid & 31;
    int wid  = tid >> 5;

    int base = tid * 8;
    int v[8];
    int s = 0;
#pragma unroll
    for (int k = 0; k < 8; ++k) { v[k] = g_cnt[base + k]; s += v[k]; }

    int x = s;
#pragma unroll
    for (int d = 1; d < 32; d <<= 1) {
        int y = __shfl_up_sync(0xffffffffu, x, d);
        if (lane >= d) x += y;
    }
    if (lane == 31) warp_sums[wid] = x;
    __syncthreads();
    if (wid == 0) {
        int w = warp_sums[lane];
        int xx = w;
#pragma unroll
        for (int d = 1; d < 32; d <<= 1) {
            int y = __shfl_up_sync(0xffffffffu, xx, d);
            if (lane >= d) xx += y;
        }
        warp_sums[lane] = xx;
    }
    __syncthreads();

    int warp_excl = (wid == 0) ? 0 : warp_sums[wid - 1];
    int run = warp_excl + (x - s);
#pragma unroll
    for (int k = 0; k < 8; ++k) { g_off[base + k] = run; run += v[k]; }
    if (tid == 1023) g_off[NPTS] = run;
}

// ---------------------------------------------------------------------------
// Pass F: emit (blocks < EMIT_BLOCKS) + tail fill (blocks >= EMIT_BLOCKS).
// Emit: one warp per row; lane L owns mask words [8L, 8L+8) i.e. cols
// [256L, 256L+256) -> row-major order preserved. Output is float32.
// ---------------------------------------------------------------------------
__global__ void emit_fill_kernel(float* __restrict__ out) {
    if (blockIdx.x >= EMIT_BLOCKS) {
        int b  = blockIdx.x - EMIT_BLOCKS;
        int e0 = (b * 256 + threadIdx.x) * 4;
        int total = g_off[NPTS];
        if (e0 + 4 > total) {
            if (e0 >= total) {
                float4 v = make_float4(-1.0f, -1.0f, -1.0f, -1.0f);
                *(float4*)(out + e0)        = v;
                *(float4*)(out + MAXE + e0) = v;
            } else {
#pragma unroll
                for (int k = 0; k < 4; ++k) {
                    if (e0 + k >= total) {
                        out[e0 + k]        = -1.0f;
                        out[MAXE + e0 + k] = -1.0f;
                    }
                }
            }
        }
        return;
    }

    int gwarp = (blockIdx.x * blockDim.x + threadIdx.x) >> 5;
    int lane  = threadIdx.x & 31;
    const int i = gwarp;

    const uint4* mrow = (const uint4*)(g_mask + (size_t)i * WPR);
    uint4 a = mrow[lane * 2 + 0];
    uint4 b = mrow[lane * 2 + 1];
    unsigned w[8] = {a.x, a.y, a.z, a.w, b.x, b.y, b.z, b.w};

    int pc = 0;
#pragma unroll
    for (int k = 0; k < 8; ++k) pc += __popc(w[k]);

    int x = pc;
#pragma unroll
    for (int d = 1; d < 32; d <<= 1) {
        int y = __shfl_up_sync(0xffffffffu, x, d);
        if (lane >= d) x += y;
    }
    int off = g_off[i] + (x - pc);

    float fi = (float)i;
    int colbase = lane * 256;
#pragma unroll
    for (int k = 0; k < 8; ++k) {
        unsigned ww = w[k];
        int cb = colbase + k * 32;
        while (ww) {
            int bit = __ffs(ww) - 1;
            out[off]        = fi;                  // rows plane
            out[MAXE + off] = (float)(cb + bit);   // cols plane
            ++off;
            ww &= ww - 1;
        }
    }
}

extern "C" void kernel_launch(void* const* d_in, const int* in_sizes, int n_in,
                              void* d_out, int out_size) {
    const float* pos = (const float*)d_in[0];
    float* out = (float*)d_out;

    zero_kernel<<<1, 1024>>>();
    pack_kernel<<<(NPTS + 255) / 256, 256>>>(pos);
    cell_scan_kernel<<<1, 1024>>>();
    scatter_kernel<<<(NPTS + 255) / 256, 256>>>();
    mask_cell_kernel<<<1024, 256>>>();         // 1 warp per row
    scan_kernel<<<1, 1024>>>();
    emit_fill_kernel<<<EMIT_BLOCKS + FILL_BLOCKS, 256>>>(out);
}